// round 2
// baseline (speedup 1.0000x reference)
#include <cuda_runtime.h>
#include <math.h>

// ---------------- problem constants ----------------
#define BB   2
#define CC   256
#define HH   8
#define HDIM 32
#define TT   16
#define SSQ  512
#define DFFN 1024
#define TSZ  (TT*SSQ)          // 8192
#define ACTN (BB*CC*TSZ)       // 4,194,304 floats
#define NPOS (BB*TSZ)          // 16384 positions

// ---------------- scratch (device globals; no allocations allowed) ----------
__device__ float g_src2[ACTN];
__device__ float g_qk[ACTN];
__device__ float g_qkenc[ACTN];
__device__ float g_qb[ACTN];
__device__ float g_kb[ACTN];
__device__ float g_vb[ACTN];
__device__ float g_vals[ACTN];
__device__ float g_h[BB*DFFN*TSZ];   // 16,777,216 floats

// ---------------- LayerNorm over channel dim of [B,C,T,S] -------------------
__global__ void ln_kernel(const float* __restrict__ x,
                          const float* __restrict__ gamma,
                          const float* __restrict__ beta,
                          float* __restrict__ y)
{
    int p = blockIdx.x * blockDim.x + threadIdx.x;   // 0..NPOS-1
    if (p >= NPOS) return;
    int b  = p / TSZ;
    int pi = p - b * TSZ;
    const float* xb = x + (size_t)b * CC * TSZ + pi;
    float s = 0.f, ss = 0.f;
    #pragma unroll 8
    for (int c = 0; c < CC; c++) {
        float v = xb[(size_t)c * TSZ];
        s  += v;
        ss += v * v;
    }
    float m   = s * (1.0f / CC);
    float var = ss * (1.0f / CC) - m * m;
    float r   = rsqrtf(var + 1e-5f);
    float* yb = y + (size_t)b * CC * TSZ + pi;
    #pragma unroll 8
    for (int c = 0; c < CC; c++) {
        float v = xb[(size_t)c * TSZ];
        yb[(size_t)c * TSZ] = (v - m) * r * __ldg(&gamma[c]) + __ldg(&beta[c]);
    }
}

// ---------------- elementwise add (float4) ----------------------------------
__global__ void add4_kernel(const float* __restrict__ a,
                            const float* __restrict__ b,
                            float* __restrict__ o, int n4)
{
    int i = blockIdx.x * blockDim.x + threadIdx.x;
    if (i < n4) {
        float4 av = ((const float4*)a)[i];
        float4 bv = ((const float4*)b)[i];
        float4 ov;
        ov.x = av.x + bv.x; ov.y = av.y + bv.y;
        ov.z = av.z + bv.z; ov.w = av.w + bv.w;
        ((float4*)o)[i] = ov;
    }
}

// ---------------- GEMM: Y[b] = W (MxK) @ X[b] (K x 8192) --------------------
// MODE bit0: +bias   bit1: relu   bit2: residual accumulate into Y
template<int MODE>
__global__ __launch_bounds__(256, 1)
void gemm_kernel(const float* __restrict__ W, const float* __restrict__ bias,
                 const float* __restrict__ X, float* __restrict__ Y,
                 int M, int K)
{
    constexpr int BM = 128, BN = 128, BK = 8;
    __shared__ float As[BK][BM];
    __shared__ float Bs[BK][BN];

    const int tid = threadIdx.x;
    const int bx = blockIdx.x, by = blockIdx.y, bz = blockIdx.z;

    const float* Wb = W + (size_t)by * BM * K;
    const float* Xb = X + (size_t)bz * K * TSZ + bx * BN;
    float*       Yb = Y + (size_t)bz * M * TSZ + (size_t)by * BM * TSZ + bx * BN;

    const int aRow = tid >> 1;
    const int aCol = (tid & 1) * 4;
    const int bRow = tid >> 5;
    const int bCol = (tid & 31) * 4;
    const int tx = tid & 15;
    const int ty = tid >> 4;

    float acc[8][8];
    #pragma unroll
    for (int i = 0; i < 8; i++)
        #pragma unroll
        for (int j = 0; j < 8; j++) acc[i][j] = 0.f;

    for (int k0 = 0; k0 < K; k0 += BK) {
        float4 a = *(const float4*)(Wb + (size_t)aRow * K + k0 + aCol);
        As[aCol + 0][aRow] = a.x;
        As[aCol + 1][aRow] = a.y;
        As[aCol + 2][aRow] = a.z;
        As[aCol + 3][aRow] = a.w;
        float4 bvv = *(const float4*)(Xb + (size_t)(k0 + bRow) * TSZ + bCol);
        *(float4*)(&Bs[bRow][bCol]) = bvv;
        __syncthreads();

        #pragma unroll
        for (int kk = 0; kk < BK; kk++) {
            float af[8], bf[8];
            *(float4*)(af)     = *(const float4*)(&As[kk][ty * 8]);
            *(float4*)(af + 4) = *(const float4*)(&As[kk][ty * 8 + 4]);
            *(float4*)(bf)     = *(const float4*)(&Bs[kk][tx * 8]);
            *(float4*)(bf + 4) = *(const float4*)(&Bs[kk][tx * 8 + 4]);
            #pragma unroll
            for (int i = 0; i < 8; i++)
                #pragma unroll
                for (int j = 0; j < 8; j++)
                    acc[i][j] += af[i] * bf[j];
        }
        __syncthreads();
    }

    #pragma unroll
    for (int i = 0; i < 8; i++) {
        int row = ty * 8 + i;
        float bia = (MODE & 1) ? __ldg(&bias[by * BM + row]) : 0.f;
        float* yr = Yb + (size_t)row * TSZ + tx * 8;
        #pragma unroll
        for (int jj = 0; jj < 8; jj += 4) {
            float4 v;
            v.x = acc[i][jj + 0] + bia;
            v.y = acc[i][jj + 1] + bia;
            v.z = acc[i][jj + 2] + bia;
            v.w = acc[i][jj + 3] + bia;
            if (MODE & 2) {
                v.x = fmaxf(v.x, 0.f); v.y = fmaxf(v.y, 0.f);
                v.z = fmaxf(v.z, 0.f); v.w = fmaxf(v.w, 0.f);
            }
            if (MODE & 4) {
                float4 r = *(const float4*)(yr + jj);
                v.x += r.x; v.y += r.y; v.z += r.z; v.w += r.w;
            }
            *(float4*)(yr + jj) = v;
        }
    }
}

// ---------------- distance-gated attention ----------------------------------
// One CTA per (b,h,t). K/V/coords/mask in smem; one query per thread,
// online (flash-style) softmax over all 512 keys.
// mask is read as 32-bit words (covers both int32 and float32 harness dtypes:
// any nonzero bit pattern == True).
#define SPAD 33
#define ATTN_SMEM_FLOATS (2*SSQ*SPAD + SSQ*3 + SSQ)
#define ATTN_SMEM_BYTES  (ATTN_SMEM_FLOATS*4)

__global__ __launch_bounds__(512, 1)
void attn_kernel(const float* __restrict__ Q, const float* __restrict__ Kg,
                 const float* __restrict__ V, const float* __restrict__ coord,
                 const unsigned int* __restrict__ mask,
                 float* __restrict__ out)
{
    extern __shared__ float sm[];
    float* Ks = sm;                      // [512][33]
    float* Vs = Ks + SSQ * SPAD;         // [512][33]
    float* cs = Vs + SSQ * SPAD;         // [512][3]
    float* ms = cs + SSQ * 3;            // [512]

    int blk = blockIdx.x;                // b*H*T + h*T + t
    int b = blk / (HH * TT);
    int rem = blk - b * (HH * TT);
    int h = rem / TT;
    int t = rem - h * TT;

    int tid = threadIdx.x;               // 0..511
    size_t base = ((size_t)(b * CC + h * HDIM)) * TSZ + (size_t)t * SSQ;

    // cooperative loads: coalesced global, conflict-free smem
    #pragma unroll
    for (int d = 0; d < HDIM; d++) {
        Ks[tid * SPAD + d] = Kg[base + (size_t)d * TSZ + tid];
        Vs[tid * SPAD + d] = V [base + (size_t)d * TSZ + tid];
    }
    size_t cbase = ((size_t)(b * TT + t) * SSQ) * 3;
    for (int i = tid; i < SSQ * 3; i += 512) cs[i] = coord[cbase + i];
    ms[tid] = (mask[(size_t)(b * TT + t) * SSQ + tid] != 0u) ? 1.f : 0.f;
    __syncthreads();

    const int q = tid;
    float qv[HDIM];
    #pragma unroll
    for (int d = 0; d < HDIM; d++) qv[d] = Q[base + (size_t)d * TSZ + q];
    float qx = cs[q * 3 + 0], qy = cs[q * 3 + 1], qz = cs[q * 3 + 2];

    const float SCL = 0.17677669529663687f;  // 1/sqrt(32)
    float m = -3.4e38f, l = 0.f;
    float acc[HDIM];
    #pragma unroll
    for (int d = 0; d < HDIM; d++) acc[d] = 0.f;

    for (int j = 0; j < SSQ; j++) {
        const float* kr = &Ks[j * SPAD];
        float dot = 0.f;
        #pragma unroll
        for (int d = 0; d < HDIM; d++) dot += qv[d] * kr[d];
        float dx = qx - cs[j * 3 + 0];
        float dy = qy - cs[j * 3 + 1];
        float dz = qz - cs[j * 3 + 2];
        float d2 = dx * dx + dy * dy + dz * dz;
        float logit = (d2 < 625.0f) ? dot * SCL : 0.0f;   // gate (sqrt(d2)<25)
        if (ms[j] > 0.5f) logit = -9e15f;                 // padded key

        const float* vr = &Vs[j * SPAD];
        if (logit > m) {
            float sc = __expf(m - logit);
            l = l * sc + 1.f;
            #pragma unroll
            for (int d = 0; d < HDIM; d++) acc[d] = acc[d] * sc + vr[d];
            m = logit;
        } else {
            float p = __expf(logit - m);
            l += p;
            #pragma unroll
            for (int d = 0; d < HDIM; d++) acc[d] += p * vr[d];
        }
    }
    float inv = 1.f / l;
    #pragma unroll
    for (int d = 0; d < HDIM; d++)
        out[base + (size_t)d * TSZ + q] = acc[d] * inv;
}

// ---------------- orchestration ---------------------------------------------
extern "C" void kernel_launch(void* const* d_in, const int* in_sizes, int n_in,
                              void* d_out, int out_size)
{
    const float* decoder = (const float*)d_in[0];
    const float* encoder = (const float*)d_in[1];
    const float* pos     = (const float*)d_in[2];
    const float* coord   = (const float*)d_in[3];
    const unsigned int* mask = (const unsigned int*)d_in[4];
    const float* Wq = (const float*)d_in[5];
    const float* bq = (const float*)d_in[6];
    const float* Wk = (const float*)d_in[7];
    const float* bk = (const float*)d_in[8];
    const float* Wv = (const float*)d_in[9];
    const float* bv = (const float*)d_in[10];
    const float* Wo = (const float*)d_in[11];
    const float* bo = (const float*)d_in[12];
    const float* W1 = (const float*)d_in[13];
    const float* b1 = (const float*)d_in[14];
    const float* W2 = (const float*)d_in[15];
    const float* b2 = (const float*)d_in[16];
    const float* lng = (const float*)d_in[17];
    const float* lnb = (const float*)d_in[18];
    float* out = (float*)d_out;

    float *src2, *qk, *qkenc, *qb, *kb, *vb, *vals, *hbuf;
    cudaGetSymbolAddress((void**)&src2,  g_src2);
    cudaGetSymbolAddress((void**)&qk,    g_qk);
    cudaGetSymbolAddress((void**)&qkenc, g_qkenc);
    cudaGetSymbolAddress((void**)&qb,    g_qb);
    cudaGetSymbolAddress((void**)&kb,    g_kb);
    cudaGetSymbolAddress((void**)&vb,    g_vb);
    cudaGetSymbolAddress((void**)&vals,  g_vals);
    cudaGetSymbolAddress((void**)&hbuf,  g_h);

    cudaFuncSetAttribute((const void*)attn_kernel,
                         cudaFuncAttributeMaxDynamicSharedMemorySize,
                         ATTN_SMEM_BYTES);

    // dec = decoder (residual stream lives in d_out)
    cudaMemcpyAsync(out, decoder, sizeof(float) * ACTN, cudaMemcpyDeviceToDevice);
    // qkenc = encoder + pos (reused by both layers)
    add4_kernel<<<(ACTN/4 + 255)/256, 256>>>(encoder, pos, qkenc, ACTN/4);

    dim3 gp(TSZ/128, CC/128, BB);       // (64, 2, 2)
    dim3 gf(TSZ/128, DFFN/128, BB);     // (64, 8, 2)
    dim3 lnGrid(NPOS/128);
    int  attnBlocks = BB * HH * TT;     // 256

    for (int i = 0; i < 2; i++) {
        const float* Wq_l = Wq + (size_t)i*CC*CC;   const float* bq_l = bq + (size_t)i*CC;
        const float* Wk_l = Wk + (size_t)i*CC*CC;   const float* bk_l = bk + (size_t)i*CC;
        const float* Wv_l = Wv + (size_t)i*CC*CC;   const float* bv_l = bv + (size_t)i*CC;
        const float* Wo_l = Wo + (size_t)i*CC*CC;   const float* bo_l = bo + (size_t)i*CC;
        const float* W1_l = W1 + (size_t)i*DFFN*CC; const float* b1_l = b1 + (size_t)i*DFFN;
        const float* W2_l = W2 + (size_t)i*CC*DFFN; const float* b2_l = b2 + (size_t)i*CC;
        const float* g0 = lng + (size_t)(i*3+0)*CC; const float* be0 = lnb + (size_t)(i*3+0)*CC;
        const float* g1 = lng + (size_t)(i*3+1)*CC; const float* be1 = lnb + (size_t)(i*3+1)*CC;
        const float* g2 = lng + (size_t)(i*3+2)*CC; const float* be2 = lnb + (size_t)(i*3+2)*CC;

        // ---- block 1: self-attention, q/k = LN(dec)+pos, v = LN(dec) ----
        ln_kernel<<<lnGrid, 128>>>(out, g0, be0, src2);
        add4_kernel<<<(ACTN/4 + 255)/256, 256>>>(src2, pos, qk, ACTN/4);
        gemm_kernel<1><<<gp, 256>>>(Wq_l, bq_l, qk,   qb, CC, CC);
        gemm_kernel<1><<<gp, 256>>>(Wk_l, bk_l, qk,   kb, CC, CC);
        gemm_kernel<1><<<gp, 256>>>(Wv_l, bv_l, src2, vb, CC, CC);
        attn_kernel<<<attnBlocks, 512, ATTN_SMEM_BYTES>>>(qb, kb, vb, coord, mask, vals);
        gemm_kernel<5><<<gp, 256>>>(Wo_l, bo_l, vals, out, CC, CC);

        // ---- block 2: q/k = encoder+pos, v = LN(dec) ----
        ln_kernel<<<lnGrid, 128>>>(out, g1, be1, src2);
        gemm_kernel<1><<<gp, 256>>>(Wq_l, bq_l, qkenc, qb, CC, CC);
        gemm_kernel<1><<<gp, 256>>>(Wk_l, bk_l, qkenc, kb, CC, CC);
        gemm_kernel<1><<<gp, 256>>>(Wv_l, bv_l, src2,  vb, CC, CC);
        attn_kernel<<<attnBlocks, 512, ATTN_SMEM_BYTES>>>(qb, kb, vb, coord, mask, vals);
        gemm_kernel<5><<<gp, 256>>>(Wo_l, bo_l, vals, out, CC, CC);

        // ---- FFN ----
        ln_kernel<<<lnGrid, 128>>>(out, g2, be2, src2);
        gemm_kernel<3><<<gf, 256>>>(W1_l, b1_l, src2, hbuf, DFFN, CC);
        gemm_kernel<5><<<gp, 256>>>(W2_l, b2_l, hbuf, out,  CC, DFFN);
    }
}

// round 3
// speedup vs baseline: 1.3721x; 1.3721x over previous
#include <cuda_runtime.h>
#include <cstdint>
#include <math.h>

// ---------------- problem constants ----------------
#define BB   2
#define CC   256
#define HH   8
#define HDIM 32
#define TT   16
#define SSQ  512
#define DFFN 1024
#define TSZ  (TT*SSQ)          // 8192
#define ACTN (BB*CC*TSZ)       // 4,194,304 floats
#define NPOS (BB*TSZ)          // 16384 positions

// ---------------- scratch (device globals; no allocations allowed) ----------
__device__ float g_src2[ACTN];
__device__ float g_qk[ACTN];
__device__ float g_qkenc[ACTN];
__device__ float g_qb[ACTN];
__device__ float g_kb[ACTN];
__device__ float g_vb[ACTN];
__device__ float g_vals[ACTN];
__device__ float g_h[BB*DFFN*TSZ];   // 16,777,216 floats

// ---------------- LayerNorm over channel dim of [B,C,T,S] -------------------
__global__ void ln_kernel(const float* __restrict__ x,
                          const float* __restrict__ gamma,
                          const float* __restrict__ beta,
                          float* __restrict__ y)
{
    int p = blockIdx.x * blockDim.x + threadIdx.x;   // 0..NPOS-1
    if (p >= NPOS) return;
    int b  = p / TSZ;
    int pi = p - b * TSZ;
    const float* xb = x + (size_t)b * CC * TSZ + pi;
    float s = 0.f, ss = 0.f;
    #pragma unroll 8
    for (int c = 0; c < CC; c++) {
        float v = xb[(size_t)c * TSZ];
        s  += v;
        ss += v * v;
    }
    float m   = s * (1.0f / CC);
    float var = ss * (1.0f / CC) - m * m;
    float r   = rsqrtf(var + 1e-5f);
    float* yb = y + (size_t)b * CC * TSZ + pi;
    #pragma unroll 8
    for (int c = 0; c < CC; c++) {
        float v = xb[(size_t)c * TSZ];
        yb[(size_t)c * TSZ] = (v - m) * r * __ldg(&gamma[c]) + __ldg(&beta[c]);
    }
}

// ---------------- elementwise add (float4) ----------------------------------
__global__ void add4_kernel(const float* __restrict__ a,
                            const float* __restrict__ b,
                            float* __restrict__ o, int n4)
{
    int i = blockIdx.x * blockDim.x + threadIdx.x;
    if (i < n4) {
        float4 av = ((const float4*)a)[i];
        float4 bv = ((const float4*)b)[i];
        float4 ov;
        ov.x = av.x + bv.x; ov.y = av.y + bv.y;
        ov.z = av.z + bv.z; ov.w = av.w + bv.w;
        ((float4*)o)[i] = ov;
    }
}

// ---------------- TF32 tensor-core GEMM -------------------------------------
// Y[b] = W (MxK) @ X[b] (K x 8192).  MODE bit0:+bias  bit1:relu  bit2:+=residual
// CTA tile 128x128x16, 8 warps (64x32 per warp), double-buffered smem,
// mma.sync.aligned.m16n8k8.row.col.f32.tf32.tf32.f32

__device__ __forceinline__ uint32_t f2tf(float x) {
    uint32_t u;
    asm("cvt.rna.tf32.f32 %0, %1;" : "=r"(u) : "f"(x));
    return u;
}

template<int MODE>
__global__ __launch_bounds__(256)
void gemm_tf32(const float* __restrict__ W, const float* __restrict__ bias,
               const float* __restrict__ X, float* __restrict__ Y,
               int M, int K)
{
    constexpr int BM = 128, BN = 128, BK = 16;
    __shared__ uint32_t As[2][BM][BK + 4];   // row-major (k contiguous), stride 20
    __shared__ uint32_t Bs[2][BK][BN + 8];   // k-major (n contiguous), stride 136

    const int tid  = threadIdx.x;
    const int bx = blockIdx.x, by = blockIdx.y, bz = blockIdx.z;
    const int lane = tid & 31;
    const int gid  = lane >> 2;      // 0..7
    const int tig  = lane & 3;       // 0..3
    const int warp = tid >> 5;       // 0..7
    const int wm = (warp & 1) * 64;  // warp row offset
    const int wn = (warp >> 1) * 32; // warp col offset

    const float* Wb = W + (size_t)by * BM * K;
    const float* Xb = X + (size_t)bz * K * TSZ + bx * BN;
    float*       Yb = Y + (size_t)bz * M * TSZ + (size_t)by * BM * TSZ + bx * BN;

    // global-load assignments
    const int arow0 = tid >> 2;          // A rows: arow0, arow0+64
    const int akc   = (tid & 3) * 4;     // A k-offset (float4)
    const int bkr0  = tid >> 5;          // B k-rows: bkr0, bkr0+8
    const int bnc   = (tid & 31) * 4;    // B n-offset (float4)

    float acc[4][4][4];
    #pragma unroll
    for (int mi = 0; mi < 4; mi++)
        #pragma unroll
        for (int nj = 0; nj < 4; nj++)
            #pragma unroll
            for (int r = 0; r < 4; r++) acc[mi][nj][r] = 0.f;

    // prefetch iter 0
    float4 pa0 = *(const float4*)(Wb + (size_t)arow0 * K + akc);
    float4 pa1 = *(const float4*)(Wb + (size_t)(arow0 + 64) * K + akc);
    float4 pb0 = *(const float4*)(Xb + (size_t)bkr0 * TSZ + bnc);
    float4 pb1 = *(const float4*)(Xb + (size_t)(bkr0 + 8) * TSZ + bnc);

    const int nIter = K / BK;
    for (int it = 0; it < nIter; ++it) {
        const int buf = it & 1;
        // store prefetched tile (convert to tf32 on the way)
        {
            uint32_t* ar = &As[buf][arow0][akc];
            ar[0] = f2tf(pa0.x); ar[1] = f2tf(pa0.y); ar[2] = f2tf(pa0.z); ar[3] = f2tf(pa0.w);
            uint32_t* ar2 = &As[buf][arow0 + 64][akc];
            ar2[0] = f2tf(pa1.x); ar2[1] = f2tf(pa1.y); ar2[2] = f2tf(pa1.z); ar2[3] = f2tf(pa1.w);
            uint32_t* br = &Bs[buf][bkr0][bnc];
            br[0] = f2tf(pb0.x); br[1] = f2tf(pb0.y); br[2] = f2tf(pb0.z); br[3] = f2tf(pb0.w);
            uint32_t* br2 = &Bs[buf][bkr0 + 8][bnc];
            br2[0] = f2tf(pb1.x); br2[1] = f2tf(pb1.y); br2[2] = f2tf(pb1.z); br2[3] = f2tf(pb1.w);
        }
        __syncthreads();

        if (it + 1 < nIter) {
            const int k0 = (it + 1) * BK;
            pa0 = *(const float4*)(Wb + (size_t)arow0 * K + k0 + akc);
            pa1 = *(const float4*)(Wb + (size_t)(arow0 + 64) * K + k0 + akc);
            pb0 = *(const float4*)(Xb + (size_t)(k0 + bkr0) * TSZ + bnc);
            pb1 = *(const float4*)(Xb + (size_t)(k0 + bkr0 + 8) * TSZ + bnc);
        }

        // compute from smem buffer `buf`
        #pragma unroll
        for (int kk = 0; kk < 2; kk++) {
            const int kb = kk * 8 + tig;
            uint32_t a[4][4];
            #pragma unroll
            for (int mi = 0; mi < 4; mi++) {
                const int r = wm + mi * 16 + gid;
                a[mi][0] = As[buf][r][kb];
                a[mi][1] = As[buf][r + 8][kb];
                a[mi][2] = As[buf][r][kb + 4];
                a[mi][3] = As[buf][r + 8][kb + 4];
            }
            uint32_t b[4][2];
            #pragma unroll
            for (int nj = 0; nj < 4; nj++) {
                const int c = wn + nj * 8 + gid;
                b[nj][0] = Bs[buf][kk * 8 + tig][c];
                b[nj][1] = Bs[buf][kk * 8 + tig + 4][c];
            }
            #pragma unroll
            for (int mi = 0; mi < 4; mi++)
                #pragma unroll
                for (int nj = 0; nj < 4; nj++) {
                    asm volatile(
                        "mma.sync.aligned.m16n8k8.row.col.f32.tf32.tf32.f32 "
                        "{%0,%1,%2,%3}, {%4,%5,%6,%7}, {%8,%9}, {%0,%1,%2,%3};"
                        : "+f"(acc[mi][nj][0]), "+f"(acc[mi][nj][1]),
                          "+f"(acc[mi][nj][2]), "+f"(acc[mi][nj][3])
                        : "r"(a[mi][0]), "r"(a[mi][1]), "r"(a[mi][2]), "r"(a[mi][3]),
                          "r"(b[nj][0]), "r"(b[nj][1]));
                }
        }
        __syncthreads();
    }

    // epilogue
    #pragma unroll
    for (int mi = 0; mi < 4; mi++) {
        const int r0 = wm + mi * 16 + gid;
        float bia0 = 0.f, bia1 = 0.f;
        if (MODE & 1) {
            bia0 = __ldg(&bias[by * BM + r0]);
            bia1 = __ldg(&bias[by * BM + r0 + 8]);
        }
        #pragma unroll
        for (int nj = 0; nj < 4; nj++) {
            const int c = wn + nj * 8 + tig * 2;
            float2 v0 = make_float2(acc[mi][nj][0] + bia0, acc[mi][nj][1] + bia0);
            float2 v1 = make_float2(acc[mi][nj][2] + bia1, acc[mi][nj][3] + bia1);
            if (MODE & 2) {
                v0.x = fmaxf(v0.x, 0.f); v0.y = fmaxf(v0.y, 0.f);
                v1.x = fmaxf(v1.x, 0.f); v1.y = fmaxf(v1.y, 0.f);
            }
            float* p0 = Yb + (size_t)r0 * TSZ + c;
            float* p1 = Yb + (size_t)(r0 + 8) * TSZ + c;
            if (MODE & 4) {
                float2 o0 = *(const float2*)p0;
                float2 o1 = *(const float2*)p1;
                v0.x += o0.x; v0.y += o0.y;
                v1.x += o1.x; v1.y += o1.y;
            }
            *(float2*)p0 = v0;
            *(float2*)p1 = v1;
        }
    }
}

// ---------------- distance-gated attention ----------------------------------
#define SPAD 33
#define ATTN_SMEM_FLOATS (2*SSQ*SPAD + SSQ*3 + SSQ)
#define ATTN_SMEM_BYTES  (ATTN_SMEM_FLOATS*4)

__global__ __launch_bounds__(512, 1)
void attn_kernel(const float* __restrict__ Q, const float* __restrict__ Kg,
                 const float* __restrict__ V, const float* __restrict__ coord,
                 const unsigned int* __restrict__ mask,
                 float* __restrict__ out)
{
    extern __shared__ float sm[];
    float* Ks = sm;                      // [512][33]
    float* Vs = Ks + SSQ * SPAD;         // [512][33]
    float* cs = Vs + SSQ * SPAD;         // [512][3]
    float* ms = cs + SSQ * 3;            // [512]

    int blk = blockIdx.x;                // b*H*T + h*T + t
    int b = blk / (HH * TT);
    int rem = blk - b * (HH * TT);
    int h = rem / TT;
    int t = rem - h * TT;

    int tid = threadIdx.x;               // 0..511
    size_t base = ((size_t)(b * CC + h * HDIM)) * TSZ + (size_t)t * SSQ;

    #pragma unroll
    for (int d = 0; d < HDIM; d++) {
        Ks[tid * SPAD + d] = Kg[base + (size_t)d * TSZ + tid];
        Vs[tid * SPAD + d] = V [base + (size_t)d * TSZ + tid];
    }
    size_t cbase = ((size_t)(b * TT + t) * SSQ) * 3;
    for (int i = tid; i < SSQ * 3; i += 512) cs[i] = coord[cbase + i];
    ms[tid] = (mask[(size_t)(b * TT + t) * SSQ + tid] != 0u) ? 1.f : 0.f;
    __syncthreads();

    const int q = tid;
    float qv[HDIM];
    #pragma unroll
    for (int d = 0; d < HDIM; d++) qv[d] = Q[base + (size_t)d * TSZ + q];
    float qx = cs[q * 3 + 0], qy = cs[q * 3 + 1], qz = cs[q * 3 + 2];

    const float SCL = 0.17677669529663687f;  // 1/sqrt(32)
    float m = -3.4e38f, l = 0.f;
    float acc[HDIM];
    #pragma unroll
    for (int d = 0; d < HDIM; d++) acc[d] = 0.f;

    for (int j = 0; j < SSQ; j++) {
        const float* kr = &Ks[j * SPAD];
        float dot = 0.f;
        #pragma unroll
        for (int d = 0; d < HDIM; d++) dot += qv[d] * kr[d];
        float dx = qx - cs[j * 3 + 0];
        float dy = qy - cs[j * 3 + 1];
        float dz = qz - cs[j * 3 + 2];
        float d2 = dx * dx + dy * dy + dz * dz;
        float logit = (d2 < 625.0f) ? dot * SCL : 0.0f;   // gate (sqrt(d2)<25)
        if (ms[j] > 0.5f) logit = -9e15f;                 // padded key

        const float* vr = &Vs[j * SPAD];
        if (logit > m) {
            float sc = __expf(m - logit);
            l = l * sc + 1.f;
            #pragma unroll
            for (int d = 0; d < HDIM; d++) acc[d] = acc[d] * sc + vr[d];
            m = logit;
        } else {
            float p = __expf(logit - m);
            l += p;
            #pragma unroll
            for (int d = 0; d < HDIM; d++) acc[d] += p * vr[d];
        }
    }
    float inv = 1.f / l;
    #pragma unroll
    for (int d = 0; d < HDIM; d++)
        out[base + (size_t)d * TSZ + q] = acc[d] * inv;
}

// ---------------- orchestration ---------------------------------------------
extern "C" void kernel_launch(void* const* d_in, const int* in_sizes, int n_in,
                              void* d_out, int out_size)
{
    const float* decoder = (const float*)d_in[0];
    const float* encoder = (const float*)d_in[1];
    const float* pos     = (const float*)d_in[2];
    const float* coord   = (const float*)d_in[3];
    const unsigned int* mask = (const unsigned int*)d_in[4];
    const float* Wq = (const float*)d_in[5];
    const float* bq = (const float*)d_in[6];
    const float* Wk = (const float*)d_in[7];
    const float* bk = (const float*)d_in[8];
    const float* Wv = (const float*)d_in[9];
    const float* bv = (const float*)d_in[10];
    const float* Wo = (const float*)d_in[11];
    const float* bo = (const float*)d_in[12];
    const float* W1 = (const float*)d_in[13];
    const float* b1 = (const float*)d_in[14];
    const float* W2 = (const float*)d_in[15];
    const float* b2 = (const float*)d_in[16];
    const float* lng = (const float*)d_in[17];
    const float* lnb = (const float*)d_in[18];
    float* out = (float*)d_out;

    float *src2, *qk, *qkenc, *qb, *kb, *vb, *vals, *hbuf;
    cudaGetSymbolAddress((void**)&src2,  g_src2);
    cudaGetSymbolAddress((void**)&qk,    g_qk);
    cudaGetSymbolAddress((void**)&qkenc, g_qkenc);
    cudaGetSymbolAddress((void**)&qb,    g_qb);
    cudaGetSymbolAddress((void**)&kb,    g_kb);
    cudaGetSymbolAddress((void**)&vb,    g_vb);
    cudaGetSymbolAddress((void**)&vals,  g_vals);
    cudaGetSymbolAddress((void**)&hbuf,  g_h);

    cudaFuncSetAttribute((const void*)attn_kernel,
                         cudaFuncAttributeMaxDynamicSharedMemorySize,
                         ATTN_SMEM_BYTES);

    // dec = decoder (residual stream lives in d_out)
    cudaMemcpyAsync(out, decoder, sizeof(float) * ACTN, cudaMemcpyDeviceToDevice);
    // qkenc = encoder + pos (reused by both layers)
    add4_kernel<<<(ACTN/4 + 255)/256, 256>>>(encoder, pos, qkenc, ACTN/4);

    dim3 gp(TSZ/128, CC/128, BB);       // (64, 2, 2)
    dim3 gf(TSZ/128, DFFN/128, BB);     // (64, 8, 2)
    dim3 lnGrid(NPOS/128);
    int  attnBlocks = BB * HH * TT;     // 256

    for (int i = 0; i < 2; i++) {
        const float* Wq_l = Wq + (size_t)i*CC*CC;   const float* bq_l = bq + (size_t)i*CC;
        const float* Wk_l = Wk + (size_t)i*CC*CC;   const float* bk_l = bk + (size_t)i*CC;
        const float* Wv_l = Wv + (size_t)i*CC*CC;   const float* bv_l = bv + (size_t)i*CC;
        const float* Wo_l = Wo + (size_t)i*CC*CC;   const float* bo_l = bo + (size_t)i*CC;
        const float* W1_l = W1 + (size_t)i*DFFN*CC; const float* b1_l = b1 + (size_t)i*DFFN;
        const float* W2_l = W2 + (size_t)i*CC*DFFN; const float* b2_l = b2 + (size_t)i*CC;
        const float* g0 = lng + (size_t)(i*3+0)*CC; const float* be0 = lnb + (size_t)(i*3+0)*CC;
        const float* g1 = lng + (size_t)(i*3+1)*CC; const float* be1 = lnb + (size_t)(i*3+1)*CC;
        const float* g2 = lng + (size_t)(i*3+2)*CC; const float* be2 = lnb + (size_t)(i*3+2)*CC;

        // ---- block 1: self-attention, q/k = LN(dec)+pos, v = LN(dec) ----
        ln_kernel<<<lnGrid, 128>>>(out, g0, be0, src2);
        add4_kernel<<<(ACTN/4 + 255)/256, 256>>>(src2, pos, qk, ACTN/4);
        gemm_tf32<1><<<gp, 256>>>(Wq_l, bq_l, qk,   qb, CC, CC);
        gemm_tf32<1><<<gp, 256>>>(Wk_l, bk_l, qk,   kb, CC, CC);
        gemm_tf32<1><<<gp, 256>>>(Wv_l, bv_l, src2, vb, CC, CC);
        attn_kernel<<<attnBlocks, 512, ATTN_SMEM_BYTES>>>(qb, kb, vb, coord, mask, vals);
        gemm_tf32<5><<<gp, 256>>>(Wo_l, bo_l, vals, out, CC, CC);

        // ---- block 2: q/k = encoder+pos, v = LN(dec) ----
        ln_kernel<<<lnGrid, 128>>>(out, g1, be1, src2);
        gemm_tf32<1><<<gp, 256>>>(Wq_l, bq_l, qkenc, qb, CC, CC);
        gemm_tf32<1><<<gp, 256>>>(Wk_l, bk_l, qkenc, kb, CC, CC);
        gemm_tf32<1><<<gp, 256>>>(Wv_l, bv_l, src2,  vb, CC, CC);
        attn_kernel<<<attnBlocks, 512, ATTN_SMEM_BYTES>>>(qb, kb, vb, coord, mask, vals);
        gemm_tf32<5><<<gp, 256>>>(Wo_l, bo_l, vals, out, CC, CC);

        // ---- FFN ----
        ln_kernel<<<lnGrid, 128>>>(out, g2, be2, src2);
        gemm_tf32<3><<<gf, 256>>>(W1_l, b1_l, src2, hbuf, DFFN, CC);
        gemm_tf32<5><<<gp, 256>>>(W2_l, b2_l, hbuf, out,  CC, DFFN);
    }
}

// round 4
// speedup vs baseline: 3.2187x; 2.3457x over previous
#include <cuda_runtime.h>
#include <cstdint>
#include <math.h>

// ---------------- problem constants ----------------
#define BB   2
#define CC   256
#define HH   8
#define HDIM 32
#define TT   16
#define SSQ  512
#define DFFN 1024
#define TSZ  (TT*SSQ)          // 8192
#define ACTN (BB*CC*TSZ)       // 4,194,304 floats
#define NPOS (BB*TSZ)          // 16384 positions

// ---------------- scratch (device globals; no allocations allowed) ----------
__device__ float g_src2[ACTN];
__device__ float g_qk[ACTN];
__device__ float g_qkenc[ACTN];
__device__ float g_qb[ACTN];
__device__ float g_kb[ACTN];
__device__ float g_vb[ACTN];
__device__ float g_vals[ACTN];
__device__ float g_h[BB*DFFN*TSZ];   // 16,777,216 floats

// sparse-attention precompute: active = gated AND unmasked, per (b,t) tile
// layout: g_bits[bt][w][q]  (w = key-word 0..15, q = query 0..511)
__device__ unsigned g_bits[BB*TT*16*SSQ];
__device__ unsigned g_maskw[BB*TT*16];
__device__ int      g_nu[BB*TT];

// ---------------- gate/mask bit precompute (runs once per launch) -----------
__global__ void gate_kernel(const float* __restrict__ coord,
                            const unsigned* __restrict__ mask)
{
    __shared__ float cs[SSQ*3];
    __shared__ unsigned mw[16];
    int bt  = blockIdx.x;          // 0..31  (b*T + t)
    int wg  = blockIdx.y;          // 0..3   -> key words 4wg..4wg+3
    int tid = threadIdx.x;         // 0..511 (query)

    size_t cbase = (size_t)bt * SSQ * 3;
    for (int i = tid; i < SSQ*3; i += 512) cs[i] = coord[cbase + i];
    unsigned mv  = (mask[(size_t)bt*SSQ + tid] != 0u);
    unsigned bal = __ballot_sync(0xffffffffu, mv);
    if ((tid & 31) == 0) mw[tid >> 5] = bal;
    __syncthreads();

    if (wg == 0) {
        if (tid == 0) {
            int nm = 0;
            for (int w = 0; w < 16; w++) nm += __popc(mw[w]);
            g_nu[bt] = SSQ - nm;
        }
        if (tid < 16) g_maskw[bt*16 + tid] = mw[tid];
    }

    float qx = cs[tid*3], qy = cs[tid*3+1], qz = cs[tid*3+2];
    for (int w = wg*4; w < wg*4 + 4; w++) {
        unsigned bits = 0, mk = mw[w];
        #pragma unroll
        for (int bb = 0; bb < 32; bb++) {
            int j = w*32 + bb;
            float dx = qx - cs[j*3], dy = qy - cs[j*3+1], dz = qz - cs[j*3+2];
            float d2 = dx*dx + dy*dy + dz*dz;
            if (d2 < 625.0f && !((mk >> bb) & 1u)) bits |= (1u << bb);
        }
        g_bits[((size_t)bt*16 + w)*SSQ + tid] = bits;
    }
}

// ---------------- LayerNorm over channel dim (optionally fused +pos) --------
template<bool ADDPOS>
__global__ void ln_kernel(const float* __restrict__ x,
                          const float* __restrict__ gamma,
                          const float* __restrict__ beta,
                          float* __restrict__ y,
                          const float* __restrict__ pos,
                          float* __restrict__ y2)
{
    int p = blockIdx.x * blockDim.x + threadIdx.x;
    if (p >= NPOS) return;
    int b  = p / TSZ;
    int pi = p - b * TSZ;
    size_t off = (size_t)b * CC * TSZ + pi;
    const float* xb = x + off;
    float s = 0.f, ss = 0.f;
    #pragma unroll 8
    for (int c = 0; c < CC; c++) {
        float v = xb[(size_t)c * TSZ];
        s += v; ss += v * v;
    }
    float m   = s * (1.0f / CC);
    float var = ss * (1.0f / CC) - m * m;
    float r   = rsqrtf(var + 1e-5f);
    float* yb = y + off;
    #pragma unroll 8
    for (int c = 0; c < CC; c++) {
        float v  = xb[(size_t)c * TSZ];
        float nv = (v - m) * r * __ldg(&gamma[c]) + __ldg(&beta[c]);
        yb[(size_t)c * TSZ] = nv;
        if (ADDPOS) y2[off + (size_t)c * TSZ] = nv + pos[off + (size_t)c * TSZ];
    }
}

// ---------------- elementwise add (float4) ----------------------------------
__global__ void add4_kernel(const float* __restrict__ a,
                            const float* __restrict__ b,
                            float* __restrict__ o, int n4)
{
    int i = blockIdx.x * blockDim.x + threadIdx.x;
    if (i < n4) {
        float4 av = ((const float4*)a)[i];
        float4 bv = ((const float4*)b)[i];
        float4 ov;
        ov.x = av.x + bv.x; ov.y = av.y + bv.y;
        ov.z = av.z + bv.z; ov.w = av.w + bv.w;
        ((float4*)o)[i] = ov;
    }
}

// ---------------- TF32 tensor-core GEMM -------------------------------------
__device__ __forceinline__ uint32_t f2tf(float x) {
    uint32_t u;
    asm("cvt.rna.tf32.f32 %0, %1;" : "=r"(u) : "f"(x));
    return u;
}

template<int MODE>
__global__ __launch_bounds__(256)
void gemm_tf32(const float* __restrict__ W, const float* __restrict__ bias,
               const float* __restrict__ X, float* __restrict__ Y,
               int M, int K)
{
    constexpr int BM = 128, BN = 128, BK = 16;
    __shared__ uint32_t As[2][BM][BK + 4];
    __shared__ uint32_t Bs[2][BK][BN + 8];

    const int tid  = threadIdx.x;
    const int bx = blockIdx.x, by = blockIdx.y, bz = blockIdx.z;
    const int lane = tid & 31;
    const int gid  = lane >> 2;
    const int tig  = lane & 3;
    const int warp = tid >> 5;
    const int wm = (warp & 1) * 64;
    const int wn = (warp >> 1) * 32;

    const float* Wb = W + (size_t)by * BM * K;
    const float* Xb = X + (size_t)bz * K * TSZ + bx * BN;
    float*       Yb = Y + (size_t)bz * M * TSZ + (size_t)by * BM * TSZ + bx * BN;

    const int arow0 = tid >> 2;
    const int akc   = (tid & 3) * 4;
    const int bkr0  = tid >> 5;
    const int bnc   = (tid & 31) * 4;

    float acc[4][4][4];
    #pragma unroll
    for (int mi = 0; mi < 4; mi++)
        #pragma unroll
        for (int nj = 0; nj < 4; nj++)
            #pragma unroll
            for (int r = 0; r < 4; r++) acc[mi][nj][r] = 0.f;

    float4 pa0 = *(const float4*)(Wb + (size_t)arow0 * K + akc);
    float4 pa1 = *(const float4*)(Wb + (size_t)(arow0 + 64) * K + akc);
    float4 pb0 = *(const float4*)(Xb + (size_t)bkr0 * TSZ + bnc);
    float4 pb1 = *(const float4*)(Xb + (size_t)(bkr0 + 8) * TSZ + bnc);

    const int nIter = K / BK;
    for (int it = 0; it < nIter; ++it) {
        const int buf = it & 1;
        {
            uint32_t* ar = &As[buf][arow0][akc];
            ar[0] = f2tf(pa0.x); ar[1] = f2tf(pa0.y); ar[2] = f2tf(pa0.z); ar[3] = f2tf(pa0.w);
            uint32_t* ar2 = &As[buf][arow0 + 64][akc];
            ar2[0] = f2tf(pa1.x); ar2[1] = f2tf(pa1.y); ar2[2] = f2tf(pa1.z); ar2[3] = f2tf(pa1.w);
            uint32_t* br = &Bs[buf][bkr0][bnc];
            br[0] = f2tf(pb0.x); br[1] = f2tf(pb0.y); br[2] = f2tf(pb0.z); br[3] = f2tf(pb0.w);
            uint32_t* br2 = &Bs[buf][bkr0 + 8][bnc];
            br2[0] = f2tf(pb1.x); br2[1] = f2tf(pb1.y); br2[2] = f2tf(pb1.z); br2[3] = f2tf(pb1.w);
        }
        __syncthreads();

        if (it + 1 < nIter) {
            const int k0 = (it + 1) * BK;
            pa0 = *(const float4*)(Wb + (size_t)arow0 * K + k0 + akc);
            pa1 = *(const float4*)(Wb + (size_t)(arow0 + 64) * K + k0 + akc);
            pb0 = *(const float4*)(Xb + (size_t)(k0 + bkr0) * TSZ + bnc);
            pb1 = *(const float4*)(Xb + (size_t)(k0 + bkr0 + 8) * TSZ + bnc);
        }

        #pragma unroll
        for (int kk = 0; kk < 2; kk++) {
            const int kb = kk * 8 + tig;
            uint32_t a[4][4];
            #pragma unroll
            for (int mi = 0; mi < 4; mi++) {
                const int r = wm + mi * 16 + gid;
                a[mi][0] = As[buf][r][kb];
                a[mi][1] = As[buf][r + 8][kb];
                a[mi][2] = As[buf][r][kb + 4];
                a[mi][3] = As[buf][r + 8][kb + 4];
            }
            uint32_t b[4][2];
            #pragma unroll
            for (int nj = 0; nj < 4; nj++) {
                const int c = wn + nj * 8 + gid;
                b[nj][0] = Bs[buf][kk * 8 + tig][c];
                b[nj][1] = Bs[buf][kk * 8 + tig + 4][c];
            }
            #pragma unroll
            for (int mi = 0; mi < 4; mi++)
                #pragma unroll
                for (int nj = 0; nj < 4; nj++) {
                    asm volatile(
                        "mma.sync.aligned.m16n8k8.row.col.f32.tf32.tf32.f32 "
                        "{%0,%1,%2,%3}, {%4,%5,%6,%7}, {%8,%9}, {%0,%1,%2,%3};"
                        : "+f"(acc[mi][nj][0]), "+f"(acc[mi][nj][1]),
                          "+f"(acc[mi][nj][2]), "+f"(acc[mi][nj][3])
                        : "r"(a[mi][0]), "r"(a[mi][1]), "r"(a[mi][2]), "r"(a[mi][3]),
                          "r"(b[nj][0]), "r"(b[nj][1]));
                }
        }
        __syncthreads();
    }

    #pragma unroll
    for (int mi = 0; mi < 4; mi++) {
        const int r0 = wm + mi * 16 + gid;
        float bia0 = 0.f, bia1 = 0.f;
        if (MODE & 1) {
            bia0 = __ldg(&bias[by * BM + r0]);
            bia1 = __ldg(&bias[by * BM + r0 + 8]);
        }
        #pragma unroll
        for (int nj = 0; nj < 4; nj++) {
            const int c = wn + nj * 8 + tig * 2;
            float2 v0 = make_float2(acc[mi][nj][0] + bia0, acc[mi][nj][1] + bia0);
            float2 v1 = make_float2(acc[mi][nj][2] + bia1, acc[mi][nj][3] + bia1);
            if (MODE & 2) {
                v0.x = fmaxf(v0.x, 0.f); v0.y = fmaxf(v0.y, 0.f);
                v1.x = fmaxf(v1.x, 0.f); v1.y = fmaxf(v1.y, 0.f);
            }
            float* p0 = Yb + (size_t)r0 * TSZ + c;
            float* p1 = Yb + (size_t)(r0 + 8) * TSZ + c;
            if (MODE & 4) {
                float2 o0 = *(const float2*)p0;
                float2 o1 = *(const float2*)p1;
                v0.x += o0.x; v0.y += o0.y;
                v1.x += o1.x; v1.y += o1.y;
            }
            *(float2*)p0 = v0;
            *(float2*)p1 = v1;
        }
    }
}

// ---------------- sparse distance-gated attention ----------------------------
// Active keys (gated & unmasked, ~6.5%) iterated via precomputed bitmask.
// Ungated unmasked keys all have logit == 0 -> closed-form contribution via
// per-(b,t) aggregates: n0 * e^{-M} and e^{-M} * (Vsum_unmasked - Vsum_active),
// folded as per-active-key weight (e^{lg-M} - p0) plus p0 * Vsum_unmasked.
#define KPAD 36
#define ATTN_SMEM_BYTES ((SSQ*KPAD*2 + 16*33 + 32)*4 + SSQ*16*4)

__global__ __launch_bounds__(512, 1)
void attn_sparse(const float* __restrict__ Q, const float* __restrict__ Kg,
                 const float* __restrict__ V, float* __restrict__ out)
{
    extern __shared__ float sm[];
    float* Ks = sm;                          // [512][36]
    float* Vs = Ks + SSQ*KPAD;               // [512][36]
    unsigned* bits = (unsigned*)(Vs + SSQ*KPAD);  // [16][512]  (word-major)
    float* partial = (float*)(bits + SSQ*16);     // [16][33]
    float* Vsum    = partial + 16*33;             // [32]
    __shared__ unsigned mw[16];

    int blk = blockIdx.x;
    int b = blk / (HH*TT);
    int rem = blk - b*(HH*TT);
    int h = rem / TT;
    int t = rem - h*TT;
    int bt = b*TT + t;
    int tid = threadIdx.x;                   // query index
    size_t base = ((size_t)(b*CC + h*HDIM))*TSZ + (size_t)t*SSQ;

    #pragma unroll
    for (int d = 0; d < HDIM; d++) {
        Ks[tid*KPAD + d] = Kg[base + (size_t)d*TSZ + tid];
        Vs[tid*KPAD + d] = V [base + (size_t)d*TSZ + tid];
    }
    for (int i = tid; i < SSQ*16; i += 512)
        bits[i] = g_bits[(size_t)bt*16*SSQ + i];
    if (tid < 16) mw[tid] = g_maskw[bt*16 + tid];
    __syncthreads();

    // Vsum over unmasked keys (segmented reduce: 16 chunks x 32 dims)
    {
        int d = tid & 31, c = tid >> 5;
        unsigned mk = mw[c];
        float s = 0.f;
        #pragma unroll 8
        for (int jj = 0; jj < 32; jj++)
            if (!((mk >> jj) & 1u)) s += Vs[(c*32 + jj)*KPAD + d];
        partial[c*33 + d] = s;
    }
    __syncthreads();
    if (tid < 32) {
        float s = 0.f;
        #pragma unroll
        for (int c = 0; c < 16; c++) s += partial[c*33 + tid];
        Vsum[tid] = s;
    }
    int N_u = g_nu[bt];
    __syncthreads();

    float qv[HDIM];
    #pragma unroll
    for (int d = 0; d < HDIM; d++) qv[d] = Q[base + (size_t)d*TSZ + tid];

    const float SCL = 0.17677669529663687f;  // 1/sqrt(32)

    // ---- pass A: max active logit + active count ----
    float m = -3.4e38f;
    int n_act = 0;
    for (int w = 0; w < 16; w++) {
        unsigned bz = bits[w*SSQ + tid];
        n_act += __popc(bz);
        while (bz) {
            int j = w*32 + (__ffs(bz) - 1);
            bz &= bz - 1;
            const float4* k4 = (const float4*)(Ks + j*KPAD);
            float dot = 0.f;
            #pragma unroll
            for (int r = 0; r < 8; r++) {
                float4 kk = k4[r];
                dot += qv[4*r]*kk.x + qv[4*r+1]*kk.y + qv[4*r+2]*kk.z + qv[4*r+3]*kk.w;
            }
            m = fmaxf(m, dot * SCL);
        }
    }
    int n0 = N_u - n_act;                    // ungated unmasked (logit == 0)
    if (n0 > 0) m = fmaxf(m, 0.f);

    float p0 = __expf(-m);                   // e^{0 - M}
    float l  = p0 * (float)N_u;
    float acc[HDIM];
    #pragma unroll
    for (int d = 0; d < HDIM; d++) acc[d] = p0 * Vsum[d];

    // ---- pass B: weighted accumulation over active keys ----
    for (int w = 0; w < 16; w++) {
        unsigned bz = bits[w*SSQ + tid];
        while (bz) {
            int j = w*32 + (__ffs(bz) - 1);
            bz &= bz - 1;
            const float4* k4 = (const float4*)(Ks + j*KPAD);
            float dot = 0.f;
            #pragma unroll
            for (int r = 0; r < 8; r++) {
                float4 kk = k4[r];
                dot += qv[4*r]*kk.x + qv[4*r+1]*kk.y + qv[4*r+2]*kk.z + qv[4*r+3]*kk.w;
            }
            float p = __expf(dot * SCL - m) - p0;
            l += p;
            const float4* v4 = (const float4*)(Vs + j*KPAD);
            #pragma unroll
            for (int r = 0; r < 8; r++) {
                float4 vv = v4[r];
                acc[4*r]   += p * vv.x;
                acc[4*r+1] += p * vv.y;
                acc[4*r+2] += p * vv.z;
                acc[4*r+3] += p * vv.w;
            }
        }
    }

    float inv = 1.f / l;
    #pragma unroll
    for (int d = 0; d < HDIM; d++)
        out[base + (size_t)d*TSZ + tid] = acc[d] * inv;
}

// ---------------- orchestration ---------------------------------------------
extern "C" void kernel_launch(void* const* d_in, const int* in_sizes, int n_in,
                              void* d_out, int out_size)
{
    const float* decoder = (const float*)d_in[0];
    const float* encoder = (const float*)d_in[1];
    const float* pos     = (const float*)d_in[2];
    const float* coord   = (const float*)d_in[3];
    const unsigned int* mask = (const unsigned int*)d_in[4];
    const float* Wq = (const float*)d_in[5];
    const float* bq = (const float*)d_in[6];
    const float* Wk = (const float*)d_in[7];
    const float* bk = (const float*)d_in[8];
    const float* Wv = (const float*)d_in[9];
    const float* bv = (const float*)d_in[10];
    const float* Wo = (const float*)d_in[11];
    const float* bo = (const float*)d_in[12];
    const float* W1 = (const float*)d_in[13];
    const float* b1 = (const float*)d_in[14];
    const float* W2 = (const float*)d_in[15];
    const float* b2 = (const float*)d_in[16];
    const float* lng = (const float*)d_in[17];
    const float* lnb = (const float*)d_in[18];
    float* out = (float*)d_out;

    float *src2, *qk, *qkenc, *qb, *kb, *vb, *vals, *hbuf;
    cudaGetSymbolAddress((void**)&src2,  g_src2);
    cudaGetSymbolAddress((void**)&qk,    g_qk);
    cudaGetSymbolAddress((void**)&qkenc, g_qkenc);
    cudaGetSymbolAddress((void**)&qb,    g_qb);
    cudaGetSymbolAddress((void**)&kb,    g_kb);
    cudaGetSymbolAddress((void**)&vb,    g_vb);
    cudaGetSymbolAddress((void**)&vals,  g_vals);
    cudaGetSymbolAddress((void**)&hbuf,  g_h);

    cudaFuncSetAttribute((const void*)attn_sparse,
                         cudaFuncAttributeMaxDynamicSharedMemorySize,
                         ATTN_SMEM_BYTES);

    // one-time per launch: gate/mask bitmasks (shared by all 4 attn calls)
    gate_kernel<<<dim3(BB*TT, 4), 512>>>(coord, mask);

    // dec = decoder (residual stream lives in d_out)
    cudaMemcpyAsync(out, decoder, sizeof(float) * ACTN, cudaMemcpyDeviceToDevice);
    // qkenc = encoder + pos (reused by both layers)
    add4_kernel<<<(ACTN/4 + 255)/256, 256>>>(encoder, pos, qkenc, ACTN/4);

    dim3 gp(TSZ/128, CC/128, BB);       // (64, 2, 2)
    dim3 gf(TSZ/128, DFFN/128, BB);     // (64, 8, 2)
    dim3 lnGrid(NPOS/128);
    int  attnBlocks = BB * HH * TT;     // 256

    for (int i = 0; i < 2; i++) {
        const float* Wq_l = Wq + (size_t)i*CC*CC;   const float* bq_l = bq + (size_t)i*CC;
        const float* Wk_l = Wk + (size_t)i*CC*CC;   const float* bk_l = bk + (size_t)i*CC;
        const float* Wv_l = Wv + (size_t)i*CC*CC;   const float* bv_l = bv + (size_t)i*CC;
        const float* Wo_l = Wo + (size_t)i*CC*CC;   const float* bo_l = bo + (size_t)i*CC;
        const float* W1_l = W1 + (size_t)i*DFFN*CC; const float* b1_l = b1 + (size_t)i*DFFN;
        const float* W2_l = W2 + (size_t)i*CC*DFFN; const float* b2_l = b2 + (size_t)i*CC;
        const float* g0 = lng + (size_t)(i*3+0)*CC; const float* be0 = lnb + (size_t)(i*3+0)*CC;
        const float* g1 = lng + (size_t)(i*3+1)*CC; const float* be1 = lnb + (size_t)(i*3+1)*CC;
        const float* g2 = lng + (size_t)(i*3+2)*CC; const float* be2 = lnb + (size_t)(i*3+2)*CC;

        // ---- block 1: self-attention, q/k = LN(dec)+pos (fused), v = LN(dec)
        ln_kernel<true><<<lnGrid, 128>>>(out, g0, be0, src2, pos, qk);
        gemm_tf32<1><<<gp, 256>>>(Wq_l, bq_l, qk,   qb, CC, CC);
        gemm_tf32<1><<<gp, 256>>>(Wk_l, bk_l, qk,   kb, CC, CC);
        gemm_tf32<1><<<gp, 256>>>(Wv_l, bv_l, src2, vb, CC, CC);
        attn_sparse<<<attnBlocks, 512, ATTN_SMEM_BYTES>>>(qb, kb, vb, vals);
        gemm_tf32<5><<<gp, 256>>>(Wo_l, bo_l, vals, out, CC, CC);

        // ---- block 2: q/k = encoder+pos, v = LN(dec) ----
        ln_kernel<false><<<lnGrid, 128>>>(out, g1, be1, src2, nullptr, nullptr);
        gemm_tf32<1><<<gp, 256>>>(Wq_l, bq_l, qkenc, qb, CC, CC);
        gemm_tf32<1><<<gp, 256>>>(Wk_l, bk_l, qkenc, kb, CC, CC);
        gemm_tf32<1><<<gp, 256>>>(Wv_l, bv_l, src2,  vb, CC, CC);
        attn_sparse<<<attnBlocks, 512, ATTN_SMEM_BYTES>>>(qb, kb, vb, vals);
        gemm_tf32<5><<<gp, 256>>>(Wo_l, bo_l, vals, out, CC, CC);

        // ---- FFN ----
        ln_kernel<false><<<lnGrid, 128>>>(out, g2, be2, src2, nullptr, nullptr);
        gemm_tf32<3><<<gf, 256>>>(W1_l, b1_l, src2, hbuf, DFFN, CC);
        gemm_tf32<5><<<gp, 256>>>(W2_l, b2_l, hbuf, out,  CC, DFFN);
    }
}